// round 3
// baseline (speedup 1.0000x reference)
#include <cuda_runtime.h>
#include <cstdint>

#define TILE   128
#define NTH    256
#define MAX_E  800000

// ---- shared memory layout (byte offsets) ----
#define SM_ROWS 0          // int[128]
#define SM_COLS 512        // int[128]
#define SM_EIDX 1024       // int[128]
#define SM_B1   1536       // float[256]
#define SM_B2   2560       // float[128]
#define SM_A    3072       // 128 x 192 tf32, stride 196 words (784B): 100352 B
#define SM_B    103424     // weight chunk buffer: max 50176 B
#define SMEM_TOTAL 153600

__device__ int g_cnt[2];
__device__ int g_list[2 * MAX_E];

// ---------------- helpers ----------------
static __device__ __forceinline__ uint32_t smem_u32(const void* p) {
    uint32_t a;
    asm("{ .reg .u64 t; cvta.to.shared.u64 t, %1; cvt.u32.u64 %0, t; }"
        : "=r"(a) : "l"(p));
    return a;
}
static __device__ __forceinline__ uint32_t f2tf(float f) {
    uint32_t r; asm("cvt.rna.tf32.f32 %0, %1;" : "=r"(r) : "f"(f)); return r;
}
static __device__ __forceinline__ void sts128(uint32_t a, uint32_t r0, uint32_t r1,
                                              uint32_t r2, uint32_t r3) {
    asm volatile("st.shared.v4.b32 [%0], {%1,%2,%3,%4};"
                 :: "r"(a), "r"(r0), "r"(r1), "r"(r2), "r"(r3) : "memory");
}
static __device__ __forceinline__ void ldsm_x4(uint32_t r[4], uint32_t addr) {
    asm volatile("ldmatrix.sync.aligned.m8n8.x4.shared.b16 {%0,%1,%2,%3}, [%4];"
                 : "=r"(r[0]), "=r"(r[1]), "=r"(r[2]), "=r"(r[3]) : "r"(addr));
}
static __device__ __forceinline__ void ldsm_x2(uint32_t r[2], uint32_t addr) {
    asm volatile("ldmatrix.sync.aligned.m8n8.x2.shared.b16 {%0,%1}, [%2];"
                 : "=r"(r[0]), "=r"(r[1]) : "r"(addr));
}
static __device__ __forceinline__ void mma_tf32(float d[4], const uint32_t a[4],
                                                const uint32_t b[2]) {
    asm("mma.sync.aligned.m16n8k8.row.col.f32.tf32.tf32.f32 "
        "{%0,%1,%2,%3}, {%4,%5,%6,%7}, {%8,%9}, {%0,%1,%2,%3};"
        : "+f"(d[0]), "+f"(d[1]), "+f"(d[2]), "+f"(d[3])
        : "r"(a[0]), "r"(a[1]), "r"(a[2]), "r"(a[3]), "r"(b[0]), "r"(b[1]));
}
static __device__ __forceinline__ void red_add(float* p, float v) {
    asm volatile("red.global.add.f32 [%0], %1;" :: "l"(p), "f"(v) : "memory");
}

// ---------------- kernels ----------------
__global__ void reset_kernel() { g_cnt[0] = 0; g_cnt[1] = 0; }

__global__ void partition_kernel(const int* __restrict__ ei, int E) {
    int e = blockIdx.x * blockDim.x + threadIdx.x;
    bool valid = e < E;
    int r = 0, c = 0;
    if (valid) { r = ei[e]; c = ei[E + e]; }
    int lane = threadIdx.x & 31;
    bool po = valid && (r < c);   // flow_out
    bool pi = valid && (r > c);   // flow_in
    unsigned mo = __ballot_sync(0xffffffffu, po);
    unsigned mi = __ballot_sync(0xffffffffu, pi);
    int lo = __ffs(mo) - 1, li = __ffs(mi) - 1;
    int bo = 0, bi = 0;
    if (mo && lane == lo) bo = atomicAdd(&g_cnt[0], __popc(mo));
    if (mi && lane == li) bi = atomicAdd(&g_cnt[1], __popc(mi));
    if (mo) bo = __shfl_sync(0xffffffffu, bo, lo);
    if (mi) bi = __shfl_sync(0xffffffffu, bi, li);
    unsigned lt = (1u << lane) - 1u;
    if (po) g_list[bo + __popc(mo & lt)] = e;
    if (pi) g_list[MAX_E + bi + __popc(mi & lt)] = e;
}

__global__ __launch_bounds__(NTH, 1)
void mlp_kernel(const float* __restrict__ x, const int* __restrict__ ei,
                const float* __restrict__ ea,
                const float* __restrict__ W1o, const float* __restrict__ b1o,
                const float* __restrict__ W2o, const float* __restrict__ b2o,
                const float* __restrict__ W1i, const float* __restrict__ b1i,
                const float* __restrict__ W2i, const float* __restrict__ b2i,
                int E, float* __restrict__ out) {
    int flavor = blockIdx.y;
    int cnt = g_cnt[flavor];
    int base = blockIdx.x * TILE;
    if (base >= cnt) return;
    int nvalid = min(TILE, cnt - base);
    const int* list = g_list + flavor * MAX_E;
    int colOff = flavor ? 0 : 128;   // in -> [0,128), out -> [128,256)
    const float* W1 = flavor ? W1i : W1o;
    const float* b1 = flavor ? b1i : b1o;
    const float* W2 = flavor ? W2i : W2o;
    const float* b2 = flavor ? b2i : b2o;

    extern __shared__ __align__(16) char smem[];
    uint32_t sb = smem_u32(smem);
    uint32_t sbA = sb + SM_A, sbB = sb + SM_B;
    int tid = threadIdx.x, wid = tid >> 5, lane = tid & 31;

    // header: edge ids / endpoints / biases
    if (tid < TILE) {
        int e = list[base + min(tid, nvalid - 1)];
        ((int*)(smem + SM_EIDX))[tid] = e;
        ((int*)(smem + SM_ROWS))[tid] = ei[e];
        ((int*)(smem + SM_COLS))[tid] = ei[E + e];
    }
    ((float*)(smem + SM_B1))[tid] = b1[tid];
    if (tid < 128) ((float*)(smem + SM_B2))[tid] = b2[tid];
    __syncthreads();

    // ---- gather A = [x[col] | edge_attr] as tf32, row-major stride 196 words ----
    {
        int r = tid & 127, h = tid >> 7;
        int cnode = ((const int*)(smem + SM_COLS))[r];
        int eidx  = ((const int*)(smem + SM_EIDX))[r];
        const float4* xr = (const float4*)(x + (size_t)cnode * 128);
        const float4* er = (const float4*)(ea + (size_t)eidx * 64);
        #pragma unroll
        for (int q = 0; q < 24; q++) {
            int kq = h + 2 * q;                 // 0..47 (k = 4*kq)
            float4 v = (kq < 32) ? xr[kq] : er[kq - 32];
            sts128(sbA + r * 784 + kq * 16,
                   f2tf(v.x), f2tf(v.y), f2tf(v.z), f2tf(v.w));
        }
    }

    // per-lane ldmatrix bases
    uint32_t aB  = sbA + (wid * 16 + (lane & 15)) * 784 + (lane >> 4) * 16;
    uint32_t bB1 = sbB + (lane & 7) * 784 + ((lane >> 3) & 1) * 16;   // stride 196w
    uint32_t bB2 = sbB + (lane & 7) * 272 + ((lane >> 3) & 1) * 16;   // stride 68w

    // ---- GEMM1: h[128x256] = A[128x192] @ W1, streamed in 4 n-chunks of 64 ----
    float acc1[32][4];
    #pragma unroll
    for (int j = 0; j < 32; j++)
        #pragma unroll
        for (int p = 0; p < 4; p++) acc1[j][p] = 0.0f;

    #pragma unroll
    for (int c = 0; c < 4; c++) {
        __syncthreads();
        {   // load W1^T chunk: Bt[nl<64][k<192], Bt[nl][k] = W1[k][64c+nl]
            int nl = tid & 63, qb = tid >> 6;
            const float* Wp = W1 + 64 * c + nl;
            #pragma unroll
            for (int i = 0; i < 12; i++) {
                int q = qb + 4 * i;            // k-quad, k = 4q < 192
                const float* p = Wp + (size_t)(4 * q) * 256;
                sts128(sbB + nl * 784 + q * 16,
                       f2tf(p[0]), f2tf(p[256]), f2tf(p[512]), f2tf(p[768]));
            }
        }
        __syncthreads();
        for (int s = 0; s < 24; s++) {
            uint32_t af[4]; ldsm_x4(af, aB + s * 32);
            #pragma unroll
            for (int nt = 0; nt < 8; nt++) {
                uint32_t bf[2]; ldsm_x2(bf, bB1 + nt * 6272 + s * 32);
                mma_tf32(acc1[8 * c + nt], af, bf);
            }
        }
    }

    // ---- bias + ReLU + tf32-convert, h stays in acc1 registers ----
    {
        const float* b1s = (const float*)(smem + SM_B1);
        int t2 = 2 * (lane & 3);
        #pragma unroll
        for (int j = 0; j < 32; j++) {
            #pragma unroll
            for (int p = 0; p < 4; p++) {
                float v = acc1[j][p] + b1s[8 * j + t2 + (p & 1)];
                acc1[j][p] = __uint_as_float(f2tf(fmaxf(v, 0.0f)));
            }
        }
    }

    // ---- GEMM2: out2[128x128] = h @ W2, streamed in 4 k-chunks of 64 ----
    float acc2[16][4];
    #pragma unroll
    for (int j = 0; j < 16; j++)
        #pragma unroll
        for (int p = 0; p < 4; p++) acc2[j][p] = 0.0f;

    int sl0 = (lane >> 2) * 4 + ((lane & 3) >> 1);
    int sl1 = sl0 + 2;
    bool oddl = (lane & 1);

    #pragma unroll
    for (int cc = 0; cc < 4; cc++) {
        __syncthreads();
        {   // load W2^T chunk: Bt2[nl<128][kk<64], = W2[64cc+kk][nl], stride 68w
            int nl = tid & 127;
            #pragma unroll
            for (int i = 0; i < 8; i++) {
                int q = (tid >> 7) + 2 * i;    // kk-quad < 16
                const float* p = W2 + (size_t)(64 * cc + 4 * q) * 128 + nl;
                sts128(sbB + nl * 272 + q * 16,
                       f2tf(p[0]), f2tf(p[128]), f2tf(p[256]), f2tf(p[384]));
            }
        }
        __syncthreads();
        #pragma unroll
        for (int s2 = 0; s2 < 8; s2++) {
            int j = cc * 8 + s2;               // h n-tile == GEMM2 k-block
            // A-fragment from h registers via shuffles
            float v00 = __shfl_sync(0xffffffffu, acc1[j][0], sl0);
            float v01 = __shfl_sync(0xffffffffu, acc1[j][1], sl0);
            float v20 = __shfl_sync(0xffffffffu, acc1[j][2], sl0);
            float v21 = __shfl_sync(0xffffffffu, acc1[j][3], sl0);
            float w00 = __shfl_sync(0xffffffffu, acc1[j][0], sl1);
            float w01 = __shfl_sync(0xffffffffu, acc1[j][1], sl1);
            float w20 = __shfl_sync(0xffffffffu, acc1[j][2], sl1);
            float w21 = __shfl_sync(0xffffffffu, acc1[j][3], sl1);
            uint32_t af[4];
            af[0] = __float_as_uint(oddl ? v01 : v00);
            af[1] = __float_as_uint(oddl ? v21 : v20);
            af[2] = __float_as_uint(oddl ? w01 : w00);
            af[3] = __float_as_uint(oddl ? w21 : w20);
            #pragma unroll
            for (int nt = 0; nt < 16; nt++) {
                uint32_t bf[2]; ldsm_x2(bf, bB2 + nt * 2176 + s2 * 32);
                mma_tf32(acc2[nt], af, bf);
            }
        }
    }

    // ---- epilogue: scatter-add valid rows ----
    {
        const float* b2s = (const float*)(smem + SM_B2);
        const int* rows = (const int*)(smem + SM_ROWS);
        int m1 = wid * 16 + (lane >> 2);
        int m2 = m1 + 8;
        bool ok1 = m1 < nvalid, ok2 = m2 < nvalid;
        float* o1 = ok1 ? (out + (size_t)rows[m1] * 256 + colOff) : out;
        float* o2 = ok2 ? (out + (size_t)rows[m2] * 256 + colOff) : out;
        int t2 = 2 * (lane & 3);
        #pragma unroll
        for (int nt = 0; nt < 16; nt++) {
            int n0 = 8 * nt + t2;
            if (ok1) {
                red_add(o1 + n0,     acc2[nt][0] + b2s[n0]);
                red_add(o1 + n0 + 1, acc2[nt][1] + b2s[n0 + 1]);
            }
            if (ok2) {
                red_add(o2 + n0,     acc2[nt][2] + b2s[n0]);
                red_add(o2 + n0 + 1, acc2[nt][3] + b2s[n0 + 1]);
            }
        }
    }
}

// ---------------- host launch ----------------
extern "C" void kernel_launch(void* const* d_in, const int* in_sizes, int n_in,
                              void* d_out, int out_size) {
    const float* x   = (const float*)d_in[0];
    const int*   ei  = (const int*)  d_in[1];
    const float* ea  = (const float*)d_in[2];
    const float* W1o = (const float*)d_in[3];
    const float* b1o = (const float*)d_in[4];
    const float* W2o = (const float*)d_in[5];
    const float* b2o = (const float*)d_in[6];
    const float* W1i = (const float*)d_in[7];
    const float* b1i = (const float*)d_in[8];
    const float* W2i = (const float*)d_in[9];
    const float* b2i = (const float*)d_in[10];
    float* out = (float*)d_out;
    int E = in_sizes[1] / 2;

    static bool attr_set = false;
    if (!attr_set) {
        cudaFuncSetAttribute(mlp_kernel, cudaFuncAttributeMaxDynamicSharedMemorySize,
                             SMEM_TOTAL);
        attr_set = true;
    }

    cudaMemsetAsync(d_out, 0, (size_t)out_size * sizeof(float));
    reset_kernel<<<1, 1>>>();
    partition_kernel<<<(E + 255) / 256, 256>>>(ei, E);

    dim3 grid((E + TILE - 1) / TILE, 2);
    mlp_kernel<<<grid, NTH, SMEM_TOTAL>>>(x, ei, ea, W1o, b1o, W2o, b2o,
                                          W1i, b1i, W2i, b2i, E, out);
}